// round 13
// baseline (speedup 1.0000x reference)
#include <cuda_runtime.h>
#include <cstdint>

// ============================================================================
// FrequencyToSpatialCrossAttention — persistent fused attention (v6).
//  k1  : Qg = mean(X_f)                                read 402MB
//  k2a/k2b: projections; zero g_y                      tiny
//  k35p: persistent CTAs (148 = 4b x 37). Strip = 8x16 px staged to smem ONCE
//        (196KB, 6 cp.async chunks); scores from smem as chunks land; softmax;
//        y from smem; per-chunk re-stage of next strip => continuous DRAM.
//        y held in regs across strips; atomics once per CTA.   read 402MB
//  k6a/k6b: output projections                          tiny
//  k7  : broadcast                                      write 402MB
// ============================================================================

#define BATCH 4
#define CDIM  384
#define NH    8
#define NPIX  65536

typedef unsigned long long ull;

__device__ __forceinline__ ull pk(float x, float y) {
    ull r; asm("mov.b64 %0, {%1,%2};" : "=l"(r) : "f"(x), "f"(y)); return r;
}
__device__ __forceinline__ void upk(ull v, float& x, float& y) {
    asm("mov.b64 {%0,%1}, %2;" : "=f"(x), "=f"(y) : "l"(v));
}
__device__ __forceinline__ ull ffma2(ull a, ull b, ull c) {
    ull d; asm("fma.rn.f32x2 %0, %1, %2, %3;" : "=l"(d) : "l"(a), "l"(b), "l"(c));
    return d;
}
__device__ __forceinline__ uint32_t s2u(const void* p) {
    uint32_t a;
    asm("{ .reg .u64 t; cvta.to.shared.u64 t, %1; cvt.u32.u64 %0, t; }"
        : "=r"(a) : "l"(p));
    return a;
}
__device__ __forceinline__ void cpa16(uint32_t dst, const void* src) {
    asm volatile("cp.async.cg.shared.global [%0], [%1], 16;" :: "r"(dst), "l"(src));
}

__device__ float g_Qg [BATCH*CDIM];
__device__ float g_qf [BATCH*CDIM];
__device__ float g_A  [BATCH*CDIM*NH];   // [b][c][h], scale folded
__device__ float g_y  [BATCH*NH*CDIM];
__device__ float g_pre[BATCH*CDIM];
__device__ float g_out[BATCH*CDIM];

// ---------------------------------------------------------------- k1: Qg mean
__global__ void k1_mean(const float* __restrict__ Xf) {
    int bc = blockIdx.x;
    const float4* src = (const float4*)Xf + (size_t)bc * 16384;
    float s0 = 0.f, s1 = 0.f;
    #pragma unroll 8
    for (int i = threadIdx.x; i < 16384; i += 1024) {
        float4 a = src[i], b = src[i + 512];
        s0 += (a.x + a.y) + (a.z + a.w);
        s1 += (b.x + b.y) + (b.z + b.w);
    }
    float s = s0 + s1;
    __shared__ float red[512];
    red[threadIdx.x] = s;
    __syncthreads();
    for (int o = 256; o > 0; o >>= 1) {
        if (threadIdx.x < o) red[threadIdx.x] += red[threadIdx.x + o];
        __syncthreads();
    }
    if (threadIdx.x == 0) g_Qg[bc] = red[0] * (1.f / 65536.f);
}

// -------------------------------------- k2a: qf = Qg@Wq^T + bq  (coalesced)
__global__ void k2a(const float* __restrict__ Wq, const float* __restrict__ bq) {
    int b = blockIdx.x, tid = threadIdx.x;
    __shared__ float sq[CDIM];
    for (int i = tid; i < CDIM; i += 256) sq[i] = g_Qg[b * CDIM + i];
    __syncthreads();
    int wid = tid >> 5, lane = tid & 31;
    #pragma unroll
    for (int cc = 0; cc < 4; cc++) {
        int c = blockIdx.y * 32 + wid * 4 + cc;
        const float* w = Wq + (size_t)c * CDIM;
        float s = 0.f;
        #pragma unroll
        for (int k = 0; k < 12; k++) s += w[lane + 32 * k] * sq[lane + 32 * k];
        #pragma unroll
        for (int o = 16; o > 0; o >>= 1) s += __shfl_xor_sync(0xffffffffu, s, o);
        if (lane == 0) g_qf[b * CDIM + c] = s + bq[c];
    }
}

// ----------------- k2b: A[b,c,h] = scale * qf_h . Wk_h[:,c]; zero g_y
__global__ void k2b(const float* __restrict__ Wk) {
    int b = blockIdx.x, tid = threadIdx.x;
    __shared__ float sq[CDIM];
    for (int i = tid; i < CDIM; i += 256) sq[i] = g_qf[b * CDIM + i];
    __syncthreads();
    int c = blockIdx.y * 32 + (tid & 31);
    int h = tid >> 5;
    float a = 0.f;
    #pragma unroll 8
    for (int d = 0; d < 48; d++)
        a += sq[h * 48 + d] * Wk[(size_t)(h * 48 + d) * CDIM + c];
    g_A[(size_t)(b * CDIM + c) * 8 + h] = a * 0.14433756729740643f;  // 48^-0.5
    if (blockIdx.y == 0)
        for (int i = tid; i < NH * CDIM; i += 256) g_y[b * NH * CDIM + i] = 0.f;
}

// --------------------- k35p: persistent fused scores+softmax+y
// smem layout (floats): x chunks [6][64][132] @0 (50688), score partials/
// weights sP [2][8][128] @50688 (2048), reduce scratch [8][512] @52736 (4096).
// Total 56832 floats = 227,328 B. 1 CTA/SM.
#define CHW 8448          // 64*132 floats per chunk
#define SPO 50688
#define SCO 52736
__global__ void __launch_bounds__(256) k35p(const float* __restrict__ Xs) {
    extern __shared__ float sm[];
    float* sP  = sm + SPO;
    float* scr = sm + SCO;
    uint32_t xu = s2u(sm);

    int bx = blockIdx.x;              // 148 = 4b * 37j
    int b = bx & 3, j = bx >> 2;
    int t = threadIdx.x;

    auto stage = [&](int sr, int st, int ch) {
        #pragma unroll
        for (int jj = 0; jj < 8; jj++) {
            int i = t + jj * 256;     // 2048 x 16B chunks
            int c = i >> 5, f = i & 31;
            int r = f >> 2, q = f & 3;
            int gi = (sr * 8 + r + 252) & 255;
            int gj = (st * 16 + q * 4 + 252) & 255;
            cpa16(xu + (uint32_t)(ch * CHW + c * 132 + r * 16 + q * 4) * 4,
                  Xs + ((size_t)(b * CDIM + ch * 64 + c) << 16) + gi * 256 + gj);
        }
    };

    // prologue: stage all 6 chunks of first strip (s = j)
    {
        int sr = j >> 4, st = j & 15;
        #pragma unroll
        for (int ch = 0; ch < 6; ch++) {
            stage(sr, st, ch);
            asm volatile("cp.async.commit_group;");
        }
    }

    float yreg[12];
    #pragma unroll
    for (int i = 0; i < 12; i++) yreg[i] = 0.f;

    const ulonglong2* Ab = (const ulonglong2*)(g_A + (size_t)b * CDIM * 8);

    for (int s = j; s < 512; s += 37) {
        int snext = s + 37;
        bool hn = snext < 512;
        int nsr = snext >> 4, nst = snext & 15;

        // ---------------- phase A: scores from smem as chunks land ----------
        int p = t & 127, half = t >> 7;
        ull acc[4];
        #pragma unroll
        for (int q = 0; q < 4; q++) acc[q] = pk(0.f, 0.f);

        for (int ch = 0; ch < 6; ch++) {
            switch (ch) {
                case 0: asm volatile("cp.async.wait_group 5;" ::: "memory"); break;
                case 1: asm volatile("cp.async.wait_group 4;" ::: "memory"); break;
                case 2: asm volatile("cp.async.wait_group 3;" ::: "memory"); break;
                case 3: asm volatile("cp.async.wait_group 2;" ::: "memory"); break;
                case 4: asm volatile("cp.async.wait_group 1;" ::: "memory"); break;
                default: asm volatile("cp.async.wait_group 0;" ::: "memory"); break;
            }
            __syncthreads();
            const float* xc = sm + ch * CHW;
            const ulonglong2* Ac = Ab + (ch * 64) * 2;
            #pragma unroll 8
            for (int cl = 0; cl < 32; cl++) {
                int c = half * 32 + cl;
                float x = xc[c * 132 + p];
                ull xx = pk(x, x);
                ulonglong2 a01 = Ac[c * 2];
                ulonglong2 a23 = Ac[c * 2 + 1];
                acc[0] = ffma2(xx, a01.x, acc[0]);
                acc[1] = ffma2(xx, a01.y, acc[1]);
                acc[2] = ffma2(xx, a23.x, acc[2]);
                acc[3] = ffma2(xx, a23.y, acc[3]);
            }
        }
        #pragma unroll
        for (int q = 0; q < 4; q++) {
            float lo, hi; upk(acc[q], lo, hi);
            sP[half * 1024 + (2 * q) * 128 + p]     = lo;
            sP[half * 1024 + (2 * q + 1) * 128 + p] = hi;
        }
        __syncthreads();

        // ---------------- softmax: warp 0, 16 (h,win) groups x 2 threads ----
        if (t < 32) {
            int g = t >> 1, sub = t & 1;
            int hh = g >> 1, win = g & 1;
            int pb = win * 64 + sub * 32;
            float buf[32];
            float m = -1e30f;
            #pragma unroll
            for (int k2 = 0; k2 < 32; k2++) {
                float v = sP[hh * 128 + pb + k2] + sP[1024 + hh * 128 + pb + k2];
                buf[k2] = v;
                m = fmaxf(m, v);
            }
            m = fmaxf(m, __shfl_xor_sync(0xffffffffu, m, 1));
            float Z = 0.f;
            #pragma unroll
            for (int k2 = 0; k2 < 32; k2++) {
                float e = __expf(buf[k2] - m);
                buf[k2] = e; Z += e;
            }
            Z += __shfl_xor_sync(0xffffffffu, Z, 1);
            float inv = 1.f / (Z * 1024.f);           // fold 1/nW
            #pragma unroll
            for (int k2 = 0; k2 < 32; k2++)
                sP[hh * 128 + pb + k2] = buf[k2] * inv;
        }
        __syncthreads();

        // ---------------- phase B: y from smem + re-stage next strip --------
        int cg = t & 15, tg = t >> 4;
        int lane = t & 31, wrp = t >> 5;
        for (int ch = 0; ch < 6; ch++) {
            const float* xc = sm + ch * CHW;
            ull yacc[4][8];
            #pragma unroll
            for (int i = 0; i < 4; i++)
                #pragma unroll
                for (int h = 0; h < 8; h++) yacc[i][h] = pk(0.f, 0.f);

            #pragma unroll
            for (int g2 = 0; g2 < 2; g2++) {
                int t4 = tg * 8 + g2 * 4;
                ull wl[8], wh[8];
                #pragma unroll
                for (int h = 0; h < 8; h++) {
                    float4 wv = *(const float4*)&sP[h * 128 + t4];
                    wl[h] = pk(wv.x, wv.y); wh[h] = pk(wv.z, wv.w);
                }
                #pragma unroll
                for (int i = 0; i < 4; i++) {
                    float4 xv = *(const float4*)&xc[(cg + 16 * i) * 132 + t4];
                    ull xl = pk(xv.x, xv.y), xh = pk(xv.z, xv.w);
                    #pragma unroll
                    for (int h = 0; h < 8; h++) {
                        yacc[i][h] = ffma2(xl, wl[h], yacc[i][h]);
                        yacc[i][h] = ffma2(xh, wh[h], yacc[i][h]);
                    }
                }
            }
            // fold to 512 block sums, accumulate into yreg
            #pragma unroll
            for (int i = 0; i < 4; i++)
                #pragma unroll
                for (int h = 0; h < 8; h++) {
                    float lo, hi; upk(yacc[i][h], lo, hi);
                    float v = lo + hi;
                    v += __shfl_xor_sync(0xffffffffu, v, 16);
                    if (lane < 16) scr[wrp * 512 + i * 128 + h * 16 + cg] = v;
                }
            __syncthreads();
            {
                float s0 = 0.f, s1 = 0.f;
                #pragma unroll
                for (int w = 0; w < 8; w++) {
                    s0 += scr[w * 512 + t];
                    s1 += scr[w * 512 + t + 256];
                }
                yreg[ch * 2]     += s0;
                yreg[ch * 2 + 1] += s1;
            }
            __syncthreads();
            if (hn) stage(nsr, nst, ch);
            asm volatile("cp.async.commit_group;");
        }
    }

    // flush y (37 adds per address)
    #pragma unroll
    for (int ch = 0; ch < 6; ch++)
        #pragma unroll
        for (int sdx = 0; sdx < 2; sdx++) {
            int o = t + sdx * 256;
            int i = o >> 7, h = (o >> 4) & 7;
            int c = ch * 64 + (o & 15) + 16 * i;
            atomicAdd(&g_y[b * NH * CDIM + h * CDIM + c], yreg[ch * 2 + sdx]);
        }
}

// ---------------------------- k6a: pre = Wv@y + bv   (warp-per-row, coalesced)
__global__ void k6a(const float* __restrict__ Wv, const float* __restrict__ bv) {
    int b = blockIdx.x, tid = threadIdx.x;
    __shared__ float sy[NH * CDIM];
    for (int i = tid; i < NH * CDIM; i += 256) sy[i] = g_y[b * NH * CDIM + i];
    __syncthreads();
    int wid = tid >> 5, lane = tid & 31;
    #pragma unroll
    for (int cc = 0; cc < 4; cc++) {
        int c = blockIdx.y * 32 + wid * 4 + cc;
        int h = c / 48;
        const float* w = Wv + (size_t)c * CDIM;
        const float* yy = &sy[h * CDIM];
        float s = 0.f;
        #pragma unroll
        for (int k = 0; k < 12; k++) s += w[lane + 32 * k] * yy[lane + 32 * k];
        #pragma unroll
        for (int o = 16; o > 0; o >>= 1) s += __shfl_xor_sync(0xffffffffu, s, o);
        if (lane == 0) g_pre[b * CDIM + c] = s + bv[c];
    }
}

// ---------------------------- k6b: out = Wo@pre + bo
__global__ void k6b(const float* __restrict__ Wo, const float* __restrict__ bo) {
    int b = blockIdx.x, tid = threadIdx.x;
    __shared__ float sp[CDIM];
    for (int i = tid; i < CDIM; i += 256) sp[i] = g_pre[b * CDIM + i];
    __syncthreads();
    int wid = tid >> 5, lane = tid & 31;
    #pragma unroll
    for (int cc = 0; cc < 4; cc++) {
        int c = blockIdx.y * 32 + wid * 4 + cc;
        const float* w = Wo + (size_t)c * CDIM;
        float s = 0.f;
        #pragma unroll
        for (int k = 0; k < 12; k++) s += w[lane + 32 * k] * sp[lane + 32 * k];
        #pragma unroll
        for (int o = 16; o > 0; o >>= 1) s += __shfl_xor_sync(0xffffffffu, s, o);
        if (lane == 0) g_out[b * CDIM + c] = s + bo[c];
    }
}

// ------------------------------------------------------------- k7: broadcast
__global__ void k7_bcast(float* __restrict__ out) {
    int plane = blockIdx.x;
    int q = blockIdx.y;
    float v = g_out[plane];
    float4 vv = make_float4(v, v, v, v);
    float4* dst = (float4*)out + (size_t)plane * 16384 + q * 4096;
    #pragma unroll 4
    for (int i = threadIdx.x; i < 4096; i += 256) dst[i] = vv;
}

// ============================================================================
extern "C" void kernel_launch(void* const* d_in, const int* in_sizes, int n_in,
                              void* d_out, int out_size) {
    const float* Xf = (const float*)d_in[0];
    const float* Xs = (const float*)d_in[1];
    const float* Wq = (const float*)d_in[2];
    const float* bq = (const float*)d_in[3];
    const float* Wk = (const float*)d_in[4];
    // d_in[5] = bk: constant per (b,h) in scores, cancels in softmax
    const float* Wv = (const float*)d_in[6];
    const float* bv = (const float*)d_in[7];
    const float* Wo = (const float*)d_in[8];
    const float* bo = (const float*)d_in[9];

    const int smem35 = 56832 * 4;   // 227,328 B
    cudaFuncSetAttribute(k35p, cudaFuncAttributeMaxDynamicSharedMemorySize,
                         smem35);

    k1_mean<<<BATCH * CDIM, 512>>>(Xf);
    k2a    <<<dim3(BATCH, 12), 256>>>(Wq, bq);
    k2b    <<<dim3(BATCH, 12), 256>>>(Wk);
    k35p   <<<148, 256, smem35>>>(Xs);
    k6a    <<<dim3(BATCH, 12), 256>>>(Wv, bv);
    k6b    <<<dim3(BATCH, 12), 256>>>(Wo, bo);
    k7_bcast<<<dim3(BATCH * CDIM, 4), 256>>>((float*)d_out);
}

// round 14
// speedup vs baseline: 1.4161x; 1.4161x over previous
#include <cuda_runtime.h>
#include <cstdint>

// ============================================================================
// FrequencyToSpatialCrossAttention — split pipeline v4 (R9 config restored).
//  k1 : Qg = mean(X_f)  (4-way MLP loads)            read 402MB
//  k2a/k2b: projections (warp-coalesced)             tiny
//  k3 : scores+softmax, 8x64 strip, 2px/thread,
//       x-duplicated packing (2 LDS.128/c)           read 402MB
//  k5 : y accum, 3-stage cp.async pipeline           read 402MB
//  k6a/k6b: output projections                       tiny
//  k7 : broadcast                                    write 402MB
// ============================================================================

#define BATCH 4
#define CDIM  384
#define NH    8
#define NPIX  65536
#define NWIN  1024

typedef unsigned long long ull;

__device__ __forceinline__ ull pk(float x, float y) {
    ull r; asm("mov.b64 %0, {%1,%2};" : "=l"(r) : "f"(x), "f"(y)); return r;
}
__device__ __forceinline__ void upk(ull v, float& x, float& y) {
    asm("mov.b64 {%0,%1}, %2;" : "=f"(x), "=f"(y) : "l"(v));
}
__device__ __forceinline__ ull ffma2(ull a, ull b, ull c) {
    ull d; asm("fma.rn.f32x2 %0, %1, %2, %3;" : "=l"(d) : "l"(a), "l"(b), "l"(c));
    return d;
}
__device__ __forceinline__ uint32_t s2u(const void* p) {
    uint32_t a;
    asm("{ .reg .u64 t; cvta.to.shared.u64 t, %1; cvt.u32.u64 %0, t; }"
        : "=r"(a) : "l"(p));
    return a;
}
__device__ __forceinline__ void cpa16(uint32_t dst, const void* src) {
    asm volatile("cp.async.cg.shared.global [%0], [%1], 16;" :: "r"(dst), "l"(src));
}

__device__ float g_S  [BATCH*NH*NPIX];   // softmaxed weights, windowed layout
__device__ float g_Qg [BATCH*CDIM];
__device__ float g_qf [BATCH*CDIM];
__device__ float g_A  [BATCH*CDIM*NH];   // [b][c][h], scale folded
__device__ float g_y  [BATCH*NH*CDIM];
__device__ float g_pre[BATCH*CDIM];
__device__ float g_out[BATCH*CDIM];

// ---------------------------------------------------------------- k1: Qg mean
// 512 threads; 4 independent float4 loads per iteration (stride 2048):
// i + {0,512,1024,1536}, i = tid + 2048k, k=0..7 -> exact single coverage.
__global__ void k1_mean(const float* __restrict__ Xf) {
    int bc = blockIdx.x;
    const float4* src = (const float4*)Xf + (size_t)bc * 16384;
    float s0 = 0.f, s1 = 0.f, s2 = 0.f, s3 = 0.f;
    #pragma unroll 8
    for (int i = threadIdx.x; i < 16384; i += 2048) {
        float4 a = src[i];
        float4 b = src[i + 512];
        float4 c = src[i + 1024];
        float4 d = src[i + 1536];
        s0 += (a.x + a.y) + (a.z + a.w);
        s1 += (b.x + b.y) + (b.z + b.w);
        s2 += (c.x + c.y) + (c.z + c.w);
        s3 += (d.x + d.y) + (d.z + d.w);
    }
    float s = (s0 + s1) + (s2 + s3);
    __shared__ float red[512];
    red[threadIdx.x] = s;
    __syncthreads();
    for (int o = 256; o > 0; o >>= 1) {
        if (threadIdx.x < o) red[threadIdx.x] += red[threadIdx.x + o];
        __syncthreads();
    }
    if (threadIdx.x == 0) g_Qg[bc] = red[0] * (1.f / 65536.f);
}

// -------------------------------------- k2a: qf = Qg@Wq^T + bq  (coalesced)
__global__ void k2a(const float* __restrict__ Wq, const float* __restrict__ bq) {
    int b = blockIdx.x, tid = threadIdx.x;
    __shared__ float sq[CDIM];
    for (int i = tid; i < CDIM; i += 256) sq[i] = g_Qg[b * CDIM + i];
    __syncthreads();
    int wid = tid >> 5, lane = tid & 31;
    #pragma unroll
    for (int cc = 0; cc < 4; cc++) {
        int c = blockIdx.y * 32 + wid * 4 + cc;
        const float* w = Wq + (size_t)c * CDIM;
        float s = 0.f;
        #pragma unroll
        for (int k = 0; k < 12; k++) s += w[lane + 32 * k] * sq[lane + 32 * k];
        #pragma unroll
        for (int o = 16; o > 0; o >>= 1) s += __shfl_xor_sync(0xffffffffu, s, o);
        if (lane == 0) g_qf[b * CDIM + c] = s + bq[c];
    }
}

// ----------------- k2b: A[b,c,h] = scale * qf_h . Wk_h[:,c]; zero g_y
__global__ void k2b(const float* __restrict__ Wk) {
    int b = blockIdx.x, tid = threadIdx.x;
    __shared__ float sq[CDIM];
    for (int i = tid; i < CDIM; i += 256) sq[i] = g_qf[b * CDIM + i];
    __syncthreads();
    int c = blockIdx.y * 32 + (tid & 31);
    int h = tid >> 5;
    float a = 0.f;
    #pragma unroll 8
    for (int d = 0; d < 48; d++)
        a += sq[h * 48 + d] * Wk[(size_t)(h * 48 + d) * CDIM + c];
    g_A[(size_t)(b * CDIM + c) * 8 + h] = a * 0.14433756729740643f;  // 48^-0.5
    if (blockIdx.y == 0)
        for (int i = tid; i < NH * CDIM; i += 256) g_y[b * NH * CDIM + i] = 0.f;
}

// ---------------- k3: scores + softmax; strip = 8 rows x 64 cols (8 windows)
// 2 px/thread (col, col+32) in the SAME c-iteration; x duplicated in regs,
// A loaded raw as head-pairs: 2 LDS.128 per channel.
__global__ void __launch_bounds__(256, 4) k3_scores(const float* __restrict__ Xs) {
    int bx = blockIdx.x;              // 512 = 4b * 32sr * 4st
    int b  = bx >> 7;
    int rem = bx & 127;
    int sr = rem >> 2;
    int st = rem & 3;
    int t = threadIdx.x;
    int r = t >> 5, col = t & 31;

    __shared__ float sA[CDIM * 8];    // raw [c][h], 12KB
    __shared__ float sS[8 * 520];     // scores [h][512], pitch 520

    for (int i = t; i < CDIM * 8; i += 256) sA[i] = g_A[b * CDIM * 8 + i];
    __syncthreads();

    int ii = sr * 8 + r;
    int jj = st * 64 + col;
    int si = (ii + 252) & 255;
    int sj0 = (jj + 252) & 255;
    int sj1 = (jj + 32 + 252) & 255;
    const float* xp = Xs + (size_t)b * CDIM * NPIX + si * 256;

    // acc[q]   = heads (2q,2q+1) for px0 ; acc[4+q] = same for px1
    ull acc[8];
    #pragma unroll
    for (int q = 0; q < 8; q++) acc[q] = pk(0.f, 0.f);

    const ulonglong2* sA2 = (const ulonglong2*)sA;
    #pragma unroll 8
    for (int c = 0; c < CDIM; c++) {
        const float* row = xp + ((size_t)c << 16);
        float x0 = row[sj0];
        float x1 = row[sj1];
        ull x00 = pk(x0, x0), x11 = pk(x1, x1);
        ulonglong2 a01 = sA2[c * 2];       // (a0,a1),(a2,a3)
        ulonglong2 a23 = sA2[c * 2 + 1];   // (a4,a5),(a6,a7)
        acc[0] = ffma2(x00, a01.x, acc[0]);
        acc[1] = ffma2(x00, a01.y, acc[1]);
        acc[2] = ffma2(x00, a23.x, acc[2]);
        acc[3] = ffma2(x00, a23.y, acc[3]);
        acc[4] = ffma2(x11, a01.x, acc[4]);
        acc[5] = ffma2(x11, a01.y, acc[5]);
        acc[6] = ffma2(x11, a23.x, acc[6]);
        acc[7] = ffma2(x11, a23.y, acc[7]);
    }

    int p0 = r * 64 + col;
    #pragma unroll
    for (int q = 0; q < 4; q++) {
        float lo, hi;
        upk(acc[q], lo, hi);
        sS[(2 * q) * 520 + p0]          = lo;
        sS[(2 * q + 1) * 520 + p0]      = hi;
        upk(acc[4 + q], lo, hi);
        sS[(2 * q) * 520 + p0 + 32]     = lo;
        sS[(2 * q + 1) * 520 + p0 + 32] = hi;
    }
    __syncthreads();

    // softmax: 64 (h,w) pairs, 2 threads each (sub = rows 0-3 / 4-7)
    if (t < 128) {
        int pair = t >> 1, sub = t & 1;
        int h = pair >> 3, w = pair & 7;
        int base = h * 520 + w * 8;
        float4 v[8];
        #pragma unroll
        for (int rr = 0; rr < 4; rr++) {
            int off = base + (sub * 4 + rr) * 64;
            v[rr * 2]     = *(const float4*)&sS[off];
            v[rr * 2 + 1] = *(const float4*)&sS[off + 4];
        }
        float m = -1e30f;
        #pragma unroll
        for (int q = 0; q < 8; q++)
            m = fmaxf(m, fmaxf(fmaxf(v[q].x, v[q].y), fmaxf(v[q].z, v[q].w)));
        m = fmaxf(m, __shfl_xor_sync(0xffffffffu, m, 1));
        float Z = 0.f;
        #pragma unroll
        for (int q = 0; q < 8; q++) {
            v[q].x = __expf(v[q].x - m); v[q].y = __expf(v[q].y - m);
            v[q].z = __expf(v[q].z - m); v[q].w = __expf(v[q].w - m);
            Z += (v[q].x + v[q].y) + (v[q].z + v[q].w);
        }
        Z += __shfl_xor_sync(0xffffffffu, Z, 1);
        float inv = 1.f / (Z * 1024.f);             // fold 1/nW

        int gwin = sr * 32 + st * 8 + w;
        size_t gbase = ((size_t)(b * 8 + h) * NWIN + gwin) * 64;
        #pragma unroll
        for (int rr = 0; rr < 4; rr++) {
            int rloc = (sub * 4 + rr) * 8;
            float4 e0 = v[rr * 2], e1 = v[rr * 2 + 1];
            e0.x *= inv; e0.y *= inv; e0.z *= inv; e0.w *= inv;
            e1.x *= inv; e1.y *= inv; e1.z *= inv; e1.w *= inv;
            *(float4*)&g_S[gbase + rloc]     = e0;
            *(float4*)&g_S[gbase + rloc + 4] = e1;
        }
    }
}

// ------------------------------ k5: y accum, 3-stage cp.async pipeline
// dynamic smem: 3 x (64*68 + 8*68) floats = 58,752 B. grid 288 = one wave.
#define XTS 4352    // 64*68
#define WTS 544     // 8*68
__global__ void __launch_bounds__(256) k5_y(const float* __restrict__ Xs) {
    extern __shared__ float dyn[];
    float* xt = dyn;               // [3][XTS]
    float* wt = dyn + 3 * XTS;     // [3][WTS]

    int unit = blockIdx.x;
    int b = unit / 72;
    int rem = unit % 72;
    int cchunk = rem / 12;
    int s = rem % 12;
    int cc0 = cchunk * 64;
    int t0 = (s * 1024) / 12, t1 = ((s + 1) * 1024) / 12;

    int tid = threadIdx.x;
    int cg = tid & 15, tg = tid >> 4;
    int lane = tid & 31, wid = tid >> 5;

    const float4* xsp0 = (const float4*)Xs + (size_t)(b * CDIM + cc0) * 16384;
    uint32_t xt_u = s2u(xt), wt_u = s2u(wt);

    ull acc[4][8];
    #pragma unroll
    for (int i = 0; i < 4; i++)
        #pragma unroll
        for (int h = 0; h < 8; h++) acc[i][h] = pk(0.f, 0.f);

    auto stage = [&](int tile, int buf) {
        uint32_t xb = xt_u + (uint32_t)buf * XTS * 4;
        uint32_t wb = wt_u + (uint32_t)buf * WTS * 4;
        #pragma unroll
        for (int j = 0; j < 4; j++) {
            int i = tid + j * 256;
            int c = i >> 4, tf4 = i & 15;
            cpa16(xb + (uint32_t)(c * 68 + tf4 * 4) * 4,
                  xsp0 + (size_t)c * 16384 + tile * 16 + tf4);
        }
        if (tid < 128) {
            int h = tid >> 4, tf4 = tid & 15;
            int p = tile * 64 + tf4 * 4;
            int sy = p >> 8, sx = p & 255;
            int iy = (sy + 4) & 255, ix = (sx + 4) & 255;
            size_t idx = ((size_t)(b * 8 + h) * NWIN + (iy >> 3) * 32 + (ix >> 3)) * 64
                         + (iy & 7) * 8 + (ix & 7);
            cpa16(wb + (uint32_t)(h * 68 + tf4 * 4) * 4, &g_S[idx]);
        }
    };

    int nt = t1 - t0;
    stage(t0, 0);
    asm volatile("cp.async.commit_group;");
    if (nt > 1) stage(t0 + 1, 1);
    asm volatile("cp.async.commit_group;");   // empty if nt==1; keeps numbering

    int t4 = tg * 4;
    for (int k = 0; k < nt; k++) {
        asm volatile("cp.async.wait_group 1;" ::: "memory");
        __syncthreads();
        if (k + 2 < nt) stage(t0 + k + 2, (k + 2) % 3);
        asm volatile("cp.async.commit_group;");   // empty when no stage

        int buf = k % 3;
        const float* xb = xt + buf * XTS;
        const float* wb = wt + buf * WTS;
        ull wlo[8], whi[8];
        #pragma unroll
        for (int h = 0; h < 8; h++) {
            float4 wv = *(const float4*)&wb[h * 68 + t4];
            wlo[h] = pk(wv.x, wv.y); whi[h] = pk(wv.z, wv.w);
        }
        #pragma unroll
        for (int i = 0; i < 4; i++) {
            float4 xv = *(const float4*)&xb[(cg + i * 16) * 68 + t4];
            ull xlo = pk(xv.x, xv.y), xhi = pk(xv.z, xv.w);
            #pragma unroll
            for (int h = 0; h < 8; h++) {
                acc[i][h] = ffma2(xlo, wlo[h], acc[i][h]);
                acc[i][h] = ffma2(xhi, whi[h], acc[i][h]);
            }
        }
    }
    __syncthreads();

    float* sred = xt;   // reuse buffer 0 region
    #pragma unroll
    for (int i = 0; i < 4; i++)
        #pragma unroll
        for (int h = 0; h < 8; h++) {
            float lo, hi; upk(acc[i][h], lo, hi);
            float vsum = lo + hi;
            vsum += __shfl_xor_sync(0xffffffffu, vsum, 16);
            if (lane < 16) sred[wid * 512 + i * 128 + h * 16 + lane] = vsum;
        }
    __syncthreads();
    #pragma unroll
    for (int o = tid; o < 512; o += 256) {
        float sm = 0.f;
        #pragma unroll
        for (int w = 0; w < 8; w++) sm += sred[w * 512 + o];
        int i = o >> 7, h = (o >> 4) & 7, c = cc0 + (o & 15) + 16 * i;
        atomicAdd(&g_y[b * NH * CDIM + h * CDIM + c], sm);
    }
}

// ---------------------------- k6a: pre = Wv@y + bv   (warp-per-row, coalesced)
__global__ void k6a(const float* __restrict__ Wv, const float* __restrict__ bv) {
    int b = blockIdx.x, tid = threadIdx.x;
    __shared__ float sy[NH * CDIM];
    for (int i = tid; i < NH * CDIM; i += 256) sy[i] = g_y[b * NH * CDIM + i];
    __syncthreads();
    int wid = tid >> 5, lane = tid & 31;
    #pragma unroll
    for (int cc = 0; cc < 4; cc++) {
        int c = blockIdx.y * 32 + wid * 4 + cc;
        int h = c / 48;
        const float* w = Wv + (size_t)c * CDIM;
        const float* yy = &sy[h * CDIM];
        float s = 0.f;
        #pragma unroll
        for (int k = 0; k < 12; k++) s += w[lane + 32 * k] * yy[lane + 32 * k];
        #pragma unroll
        for (int o = 16; o > 0; o >>= 1) s += __shfl_xor_sync(0xffffffffu, s, o);
        if (lane == 0) g_pre[b * CDIM + c] = s + bv[c];
    }
}

// ---------------------------- k6b: out = Wo@pre + bo
__global__ void k6b(const float* __restrict__ Wo, const float* __restrict__ bo) {
    int b = blockIdx.x, tid = threadIdx.x;
    __shared__ float sp[CDIM];
    for (int i = tid; i < CDIM; i += 256) sp[i] = g_pre[b * CDIM + i];
    __syncthreads();
    int wid = tid >> 5, lane = tid & 31;
    #pragma unroll
    for (int cc = 0; cc < 4; cc++) {
        int c = blockIdx.y * 32 + wid * 4 + cc;
        const float* w = Wo + (size_t)c * CDIM;
        float s = 0.f;
        #pragma unroll
        for (int k = 0; k < 12; k++) s += w[lane + 32 * k] * sp[lane + 32 * k];
        #pragma unroll
        for (int o = 16; o > 0; o >>= 1) s += __shfl_xor_sync(0xffffffffu, s, o);
        if (lane == 0) g_out[b * CDIM + c] = s + bo[c];
    }
}

// ------------------------------------------------------------- k7: broadcast
__global__ void k7_bcast(float* __restrict__ out) {
    int plane = blockIdx.x;
    int q = blockIdx.y;
    float v = g_out[plane];
    float4 vv = make_float4(v, v, v, v);
    float4* dst = (float4*)out + (size_t)plane * 16384 + q * 4096;
    #pragma unroll 4
    for (int i = threadIdx.x; i < 4096; i += 256) dst[i] = vv;
}

// ============================================================================
extern "C" void kernel_launch(void* const* d_in, const int* in_sizes, int n_in,
                              void* d_out, int out_size) {
    const float* Xf = (const float*)d_in[0];
    const float* Xs = (const float*)d_in[1];
    const float* Wq = (const float*)d_in[2];
    const float* bq = (const float*)d_in[3];
    const float* Wk = (const float*)d_in[4];
    // d_in[5] = bk: constant per (b,h) in scores, cancels in softmax
    const float* Wv = (const float*)d_in[6];
    const float* bv = (const float*)d_in[7];
    const float* Wo = (const float*)d_in[8];
    const float* bo = (const float*)d_in[9];

    const int smem5 = 3 * (XTS + WTS) * 4;   // 58,752 B
    cudaFuncSetAttribute(k5_y, cudaFuncAttributeMaxDynamicSharedMemorySize, smem5);

    k1_mean  <<<BATCH * CDIM, 512>>>(Xf);
    k2a      <<<dim3(BATCH, 12), 256>>>(Wq, bq);
    k2b      <<<dim3(BATCH, 12), 256>>>(Wk);
    k3_scores<<<512, 256>>>(Xs);
    k5_y     <<<288, 256, smem5>>>(Xs);
    k6a      <<<dim3(BATCH, 12), 256>>>(Wv, bv);
    k6b      <<<dim3(BATCH, 12), 256>>>(Wo, bo);
    k7_bcast <<<dim3(BATCH * CDIM, 4), 256>>>((float*)d_out);
}